// round 2
// baseline (speedup 1.0000x reference)
#include <cuda_runtime.h>

#define BB 2
#define CC 32
#define DD 16
#define CKK 4
#define EE 64      // CKK*DD
#define MM 512     // CC*DD
#define NN 4096    // H*W

#define TI 64
#define TJ 64
#define TM 128
#define EPAD 68

// scratch (allocation-free: device globals)
__device__ float g_K[BB*EE*NN];
__device__ float g_Q[BB*EE*NN];
__device__ float g_V[BB*MM*NN];

// ---------------------------------------------------------------------------
// Projection: 1x1x1 convs -> K (b,e,i), Q (b,e,i), V (b,m,j)
// grid: BB*DD*(NN/256) blocks of 256 threads
// ---------------------------------------------------------------------------
__global__ __launch_bounds__(256) void rsa_proj_kernel(
    const float* __restrict__ x,
    const float* __restrict__ Wk, const float* __restrict__ bk,
    const float* __restrict__ Wq, const float* __restrict__ bq,
    const float* __restrict__ Wv, const float* __restrict__ bv)
{
    __shared__ float sWk[CKK*CC], sWq[CKK*CC], sWv[CC*CC];
    __shared__ float sbk[CKK], sbq[CKK], sbv[CC];
    const int tid = threadIdx.x;
    for (int t = tid; t < CKK*CC; t += 256) { sWk[t] = Wk[t]; sWq[t] = Wq[t]; }
    for (int t = tid; t < CC*CC; t += 256) sWv[t] = Wv[t];
    if (tid < CKK) { sbk[tid] = bk[tid]; sbq[tid] = bq[tid]; }
    if (tid < CC)  sbv[tid] = bv[tid];
    __syncthreads();

    const int blk   = blockIdx.x;
    const int chunk = blk & 15;
    const int d     = (blk >> 4) & 15;
    const int b     = blk >> 8;
    const int i     = chunk * 256 + tid;

    float ka[CKK], qa[CKK], va[CC];
#pragma unroll
    for (int o = 0; o < CKK; o++) { ka[o] = sbk[o]; qa[o] = sbq[o]; }
#pragma unroll
    for (int o = 0; o < CC; o++) va[o] = sbv[o];

#pragma unroll 4
    for (int c = 0; c < CC; c++) {
        float xv = x[((b*CC + c)*DD + d)*NN + i];
#pragma unroll
        for (int o = 0; o < CKK; o++) {
            ka[o] += sWk[o*CC + c] * xv;
            qa[o] += sWq[o*CC + c] * xv;
        }
#pragma unroll
        for (int o = 0; o < CC; o++) va[o] += sWv[o*CC + c] * xv;
    }

#pragma unroll
    for (int o = 0; o < CKK; o++) {
        g_K[(b*EE + o*DD + d)*NN + i] = ka[o];
        g_Q[(b*EE + o*DD + d)*NN + i] = qa[o];
    }
#pragma unroll
    for (int o = 0; o < CC; o++)
        g_V[(b*MM + o*DD + d)*NN + i] = va[o];
}

// ---------------------------------------------------------------------------
// Fused attention: per CTA = (i-tile 64, m-chunk 128, batch).
// No running max (logits are tiny): accumulate exp(S)@V unnormalized and
// per-row sum(exp), normalize once in epilogue.
// ---------------------------------------------------------------------------
__global__ __launch_bounds__(256, 2) void rsa_attn_kernel(
    const float* __restrict__ x,
    const float* __restrict__ gamma,
    float* __restrict__ out)
{
    extern __shared__ float smem[];
    float* sK   = smem;                       // [EE][TI]       4096
    float* sQ   = smem + 4096;                // [EE][TJ]       4096
    float* sE   = smem + 8192;                // [TI][EPAD]     4352
    float* sV   = smem + 8192 + TI*EPAD;      // swizzled [TJ][TM] 8192
    float* sRed = sV + TJ*TM;                 // [TI][16]       1024
    float* sInv = sRed + TI*16;               // [TI]           64

    const int tid   = threadIdx.x;
    const int ibase = blockIdx.x * TI;
    const int mbase = blockIdx.y * TM;
    const int b     = blockIdx.z;

    const float* Kg = g_K + b*EE*NN;
    const float* Qg = g_Q + b*EE*NN;
    const float* Vg = g_V + b*MM*NN;

    // prologue: load K tile (persistent)
#pragma unroll
    for (int it = 0; it < 4; it++) {
        int f4 = it*256 + tid;
        int e  = f4 >> 4;
        int i4 = (f4 & 15) << 2;
        *(float4*)&sK[e*TI + i4] = *(const float4*)&Kg[e*NN + ibase + i4];
    }

    const int ti = tid >> 4;   // 0..15 : i-group (rows i0..i0+3)
    const int tj = tid & 15;   // 0..15 : j-group / m-group
    const int i0 = ti << 2;
    const int j0 = tj << 2;
    const int tm = tj;

    float accA[4][4] = {};     // m = 4*tm .. +3
    float accB[4][4] = {};     // m = 64 + 4*tm .. +3
    float rs[4] = {0.f, 0.f, 0.f, 0.f};

    const float4* sK4 = (const float4*)sK;
    const float4* sQ4 = (const float4*)sQ;

    for (int jt = 0; jt < NN/TJ; jt++) {
        __syncthreads();                       // prev PV done -> may overwrite sQ/sV
        const int jb = jt * TJ;

        // load Q tile
#pragma unroll
        for (int it = 0; it < 4; it++) {
            int f4 = it*256 + tid;
            int e  = f4 >> 4;
            int j4 = (f4 & 15) << 2;
            *(float4*)&sQ[e*TJ + j4] = *(const float4*)&Qg[e*NN + jb + j4];
        }
        // load V tile (swizzled transpose: word = j*TM + (((m>>2) ^ (j>>2)) & 31)*4 + (m&3))
        // NOTE: j4..j4+3 all share the same (j>>2) group -> same swizzle key jq.
#pragma unroll
        for (int it = 0; it < 8; it++) {
            int f4 = it*256 + tid;
            int m  = f4 >> 4;
            int j4 = (f4 & 15) << 2;
            float4 v = *(const float4*)&Vg[(mbase + m)*NN + jb + j4];
            int c  = m >> 2;
            int lo = m & 3;
            int sw = (((c ^ (j4 >> 2)) & 31) << 2) + lo;
            sV[(j4+0)*TM + sw] = v.x;
            sV[(j4+1)*TM + sw] = v.y;
            sV[(j4+2)*TM + sw] = v.z;
            sV[(j4+3)*TM + sw] = v.w;
        }
        __syncthreads();

        // S = K_i^T Q_j : 4x4 per thread
        float s[4][4] = {};
#pragma unroll 8
        for (int e = 0; e < EE; e++) {
            float4 k4 = sK4[e*16 + ti];   // broadcast within half-warp
            float4 q4 = sQ4[e*16 + tj];
            s[0][0] += k4.x*q4.x; s[0][1] += k4.x*q4.y; s[0][2] += k4.x*q4.z; s[0][3] += k4.x*q4.w;
            s[1][0] += k4.y*q4.x; s[1][1] += k4.y*q4.y; s[1][2] += k4.y*q4.z; s[1][3] += k4.y*q4.w;
            s[2][0] += k4.z*q4.x; s[2][1] += k4.z*q4.y; s[2][2] += k4.z*q4.z; s[2][3] += k4.z*q4.w;
            s[3][0] += k4.w*q4.x; s[3][1] += k4.w*q4.y; s[3][2] += k4.w*q4.z; s[3][3] += k4.w*q4.w;
        }
        // exp + partial rowsum + store E
#pragma unroll
        for (int r = 0; r < 4; r++) {
            float e0 = __expf(s[r][0]);
            float e1 = __expf(s[r][1]);
            float e2 = __expf(s[r][2]);
            float e3 = __expf(s[r][3]);
            rs[r] += (e0 + e1) + (e2 + e3);
            *(float4*)&sE[(i0 + r)*EPAD + j0] = make_float4(e0, e1, e2, e3);
        }
        __syncthreads();

        // O += E @ V^T : 4x8 per thread
#pragma unroll 4
        for (int j = 0; j < TJ; j++) {
            float e0 = sE[(i0+0)*EPAD + j];
            float e1 = sE[(i0+1)*EPAD + j];
            float e2 = sE[(i0+2)*EPAD + j];
            float e3 = sE[(i0+3)*EPAD + j];
            int sw = (j >> 2) & 31;
            float4 va = *(const float4*)&sV[j*TM + ((( tm       ^ sw) & 31) << 2)];
            float4 vb = *(const float4*)&sV[j*TM + ((((tm + 16) ^ sw) & 31) << 2)];
            accA[0][0] += e0*va.x; accA[0][1] += e0*va.y; accA[0][2] += e0*va.z; accA[0][3] += e0*va.w;
            accA[1][0] += e1*va.x; accA[1][1] += e1*va.y; accA[1][2] += e1*va.z; accA[1][3] += e1*va.w;
            accA[2][0] += e2*va.x; accA[2][1] += e2*va.y; accA[2][2] += e2*va.z; accA[2][3] += e2*va.w;
            accA[3][0] += e3*va.x; accA[3][1] += e3*va.y; accA[3][2] += e3*va.z; accA[3][3] += e3*va.w;
            accB[0][0] += e0*vb.x; accB[0][1] += e0*vb.y; accB[0][2] += e0*vb.z; accB[0][3] += e0*vb.w;
            accB[1][0] += e1*vb.x; accB[1][1] += e1*vb.y; accB[1][2] += e1*vb.z; accB[1][3] += e1*vb.w;
            accB[2][0] += e2*vb.x; accB[2][1] += e2*vb.y; accB[2][2] += e2*vb.z; accB[2][3] += e2*vb.w;
            accB[3][0] += e3*vb.x; accB[3][1] += e3*vb.y; accB[3][2] += e3*vb.z; accB[3][3] += e3*vb.w;
        }
    }

    // reduce rowsums across the 16 j-group threads of each row
    __syncthreads();
#pragma unroll
    for (int r = 0; r < 4; r++) sRed[(i0 + r)*16 + tj] = rs[r];
    __syncthreads();
    if (tid < TI) {
        float s = 0.f;
#pragma unroll
        for (int t = 0; t < 16; t++) s += sRed[tid*16 + t];
        sInv[tid] = 1.0f / s;
    }
    __syncthreads();

    // stage O into smem (reuse sV) as sO[m][i] for coalesced epilogue
    float* sO = sV;
#pragma unroll
    for (int r = 0; r < 4; r++) {
#pragma unroll
        for (int q = 0; q < 4; q++) {
            sO[(tm*4 + q)*TI + i0 + r]        = accA[r][q];
            sO[(64 + tm*4 + q)*TI + i0 + r]   = accB[r][q];
        }
    }
    __syncthreads();

    const float gm = gamma[0];
    for (int idx = tid; idx < TM*TI; idx += 256) {
        int m = idx >> 6;
        int i = idx & 63;
        int gi = (b*MM + mbase + m)*NN + ibase + i;
        out[gi] = gm * x[gi] + sO[m*TI + i] * sInv[i];
    }
}

// ---------------------------------------------------------------------------
extern "C" void kernel_launch(void* const* d_in, const int* in_sizes, int n_in,
                              void* d_out, int out_size)
{
    const float* x     = (const float*)d_in[0];
    const float* Wk    = (const float*)d_in[1];
    const float* bk    = (const float*)d_in[2];
    const float* Wq    = (const float*)d_in[3];
    const float* bq    = (const float*)d_in[4];
    const float* Wv    = (const float*)d_in[5];
    const float* bv    = (const float*)d_in[6];
    const float* gamma = (const float*)d_in[7];
    float* out = (float*)d_out;

    // projections
    rsa_proj_kernel<<<BB*DD*(NN/256), 256>>>(x, Wk, bk, Wq, bq, Wv, bv);

    // attention
    const int smem_bytes = (8192 + TI*EPAD + TJ*TM + TI*16 + TI) * (int)sizeof(float);
    cudaFuncSetAttribute(rsa_attn_kernel,
                         cudaFuncAttributeMaxDynamicSharedMemorySize, smem_bytes);
    dim3 grid(NN/TI, MM/TM, BB);
    rsa_attn_kernel<<<grid, 256, smem_bytes>>>(x, gamma, out);
}

// round 4
// speedup vs baseline: 7.0797x; 7.0797x over previous
#include <cuda_runtime.h>
#include <cuda_bf16.h>
#include <cstdint>

#define BB 2
#define CC 32
#define DD 16
#define CKK 4
#define EE 64      // CKK*DD
#define MM 512     // CC*DD
#define NN 4096    // H*W

// ---------------- scratch (allocation-free device globals) -----------------
__device__ __align__(128) __nv_bfloat16 g_K[BB*NN*EE];         // [b][i][e]
__device__ __align__(128) __nv_bfloat16 g_Q[BB*NN*EE];         // [b][j][e]
__device__ __align__(128) __nv_bfloat16 g_V[BB*MM*NN];         // [b][m][j]
__device__ __align__(128) __nv_bfloat16 g_P[(size_t)BB*NN*NN]; // [b][i][j] 64MB
__device__ __align__(128) float g_rsum[BB*4*NN];               // [b][quarter][i]

// ---------------- helpers ---------------------------------------------------
__device__ __forceinline__ uint32_t smem_u32(const void* p) {
    uint32_t a;
    asm("{ .reg .u64 t; cvta.to.shared.u64 t, %1; cvt.u32.u64 %0, t; }"
        : "=r"(a) : "l"(p));
    return a;
}
// swizzled byte offset for (row, 16B-chunk) in a 128B-row tile
__device__ __forceinline__ uint32_t swoff(int r, int c) {
    return (uint32_t)(r * 128 + ((c ^ (r & 7)) << 4));
}
__device__ __forceinline__ void ldm_x4(uint32_t* r, uint32_t addr) {
    asm volatile("ldmatrix.sync.aligned.m8n8.x4.shared.b16 {%0,%1,%2,%3}, [%4];"
        : "=r"(r[0]), "=r"(r[1]), "=r"(r[2]), "=r"(r[3]) : "r"(addr));
}
__device__ __forceinline__ void mma_bf16(float* c, const uint32_t* a, const uint32_t* b) {
    asm volatile("mma.sync.aligned.m16n8k16.row.col.f32.bf16.bf16.f32 "
        "{%0,%1,%2,%3}, {%4,%5,%6,%7}, {%8,%9}, {%0,%1,%2,%3};"
        : "+f"(c[0]), "+f"(c[1]), "+f"(c[2]), "+f"(c[3])
        : "r"(a[0]), "r"(a[1]), "r"(a[2]), "r"(a[3]), "r"(b[0]), "r"(b[1]));
}
__device__ __forceinline__ void cpasync16(uint32_t dst, const void* src) {
    asm volatile("cp.async.cg.shared.global [%0], [%1], 16;" :: "r"(dst), "l"(src));
}
// fast exp: e^x = 2^(x*log2e), deg-4 poly, rel err ~5e-5
__device__ __forceinline__ float fast_exp(float x) {
    float t  = x * 1.4426950408889634f;
    float rn = (t + 12582912.0f) - 12582912.0f;   // round-to-nearest int
    float f  = t - rn;
    int   n  = (int)rn;
    float p = 0.00961812910762848f;
    p = fmaf(p, f, 0.0555041086648216f);
    p = fmaf(p, f, 0.2402265069591007f);
    p = fmaf(p, f, 0.6931471805599453f);
    p = fmaf(p, f, 1.0f);
    return __int_as_float(__float_as_int(p) + (n << 23));
}

// ---------------------------------------------------------------------------
// Projection: 1x1x1 convs -> bf16 K/Q [b][i][e], V [b][m][j]
// ---------------------------------------------------------------------------
__global__ __launch_bounds__(256) void rsa_proj_kernel(
    const float* __restrict__ x,
    const float* __restrict__ Wk, const float* __restrict__ bk,
    const float* __restrict__ Wq, const float* __restrict__ bq,
    const float* __restrict__ Wv, const float* __restrict__ bv)
{
    __shared__ float sWk[CKK*CC], sWq[CKK*CC], sWv[CC*CC];
    __shared__ float sbk[CKK], sbq[CKK], sbv[CC];
    const int tid = threadIdx.x;
    for (int t = tid; t < CKK*CC; t += 256) { sWk[t] = Wk[t]; sWq[t] = Wq[t]; }
    for (int t = tid; t < CC*CC; t += 256) sWv[t] = Wv[t];
    if (tid < CKK) { sbk[tid] = bk[tid]; sbq[tid] = bq[tid]; }
    if (tid < CC)  sbv[tid] = bv[tid];
    __syncthreads();

    const int blk   = blockIdx.x;
    const int chunk = blk & 15;
    const int d     = (blk >> 4) & 15;
    const int b     = blk >> 8;
    const int i     = chunk * 256 + tid;

    float ka[CKK], qa[CKK], va[CC];
#pragma unroll
    for (int o = 0; o < CKK; o++) { ka[o] = sbk[o]; qa[o] = sbq[o]; }
#pragma unroll
    for (int o = 0; o < CC; o++) va[o] = sbv[o];

#pragma unroll 4
    for (int c = 0; c < CC; c++) {
        float xv = x[((b*CC + c)*DD + d)*NN + i];
#pragma unroll
        for (int o = 0; o < CKK; o++) {
            ka[o] += sWk[o*CC + c] * xv;
            qa[o] += sWq[o*CC + c] * xv;
        }
#pragma unroll
        for (int o = 0; o < CC; o++) va[o] += sWv[o*CC + c] * xv;
    }

#pragma unroll
    for (int o = 0; o < CKK; o++) {
        g_K[(size_t)(b*NN + i)*EE + o*DD + d] = __float2bfloat16_rn(ka[o]);
        g_Q[(size_t)(b*NN + i)*EE + o*DD + d] = __float2bfloat16_rn(qa[o]);
    }
#pragma unroll
    for (int o = 0; o < CC; o++)
        g_V[(size_t)(b*MM + o*DD + d)*NN + i] = __float2bfloat16_rn(va[o]);
}

// ---------------------------------------------------------------------------
// QK kernel: S = K_i Q_j^T (mma.sync bf16), P = exp(S) -> g_P, row partials.
// grid (32 i-tiles, 4 j-quarters, BB), 256 threads (8 warps x 16 i-rows)
// ---------------------------------------------------------------------------
#define QK_SM_K 0
#define QK_SM_Q 16384
#define QK_SM_P 32768                      // uint32[128][68]
#define QK_SMEM (32768 + 128*68*4)         // 67584

__global__ __launch_bounds__(256, 2) void rsa_qk_kernel()
{
    extern __shared__ char smem[];
    const uint32_t sb = smem_u32(smem);
    uint32_t* sP = (uint32_t*)(smem + QK_SM_P);
    const int tid  = threadIdx.x;
    const int wid  = tid >> 5, lane = tid & 31;
    const int g    = lane >> 2, q = lane & 3;
    const int b    = blockIdx.z, ibase = blockIdx.x * 128, quart = blockIdx.y;
    const int wbase = wid * 16;

    // K tile [128 i][64 e] (swizzled 128B rows) — persistent
    for (int f = tid; f < 1024; f += 256) {
        int r = f >> 3, c = f & 7;
        *(float4*)(smem + QK_SM_K + swoff(r, c)) =
            *(const float4*)(g_K + (size_t)(b*NN + ibase + r)*EE + c*8);
    }
    __syncthreads();

    // preload A fragments (K rows of this warp), 4 k-steps
    uint32_t afr[4][4];
    {
        int sg = lane >> 3, rr = lane & 7;
        int arow = wbase + ((sg & 1) << 3) + rr;
#pragma unroll
        for (int ks = 0; ks < 4; ks++)
            ldm_x4(afr[ks], sb + QK_SM_K + swoff(arow, 2*ks + (sg >> 1)));
    }

    const int brow = lane & 7, bco = lane >> 3;
    float rs0 = 0.f, rs1 = 0.f;

    for (int jt = 0; jt < 8; jt++) {
        const int jb = quart*1024 + jt*128;
        __syncthreads();   // prev iter's ldmatrix(sQ) + sP copy done
        for (int f = tid; f < 1024; f += 256) {
            int r = f >> 3, c = f & 7;
            *(float4*)(smem + QK_SM_Q + swoff(r, c)) =
                *(const float4*)(g_Q + (size_t)(b*NN + jb + r)*EE + c*8);
        }
        __syncthreads();

#pragma unroll
        for (int f = 0; f < 16; f++) {
            float acc[4] = {0.f, 0.f, 0.f, 0.f};
            uint32_t bfr[8];
            ldm_x4(bfr,     sb + QK_SM_Q + swoff(f*8 + brow, 0 + bco));
            ldm_x4(bfr + 4, sb + QK_SM_Q + swoff(f*8 + brow, 4 + bco));
            mma_bf16(acc, afr[0], bfr);
            mma_bf16(acc, afr[1], bfr + 2);
            mma_bf16(acc, afr[2], bfr + 4);
            mma_bf16(acc, afr[3], bfr + 6);
            float e0 = fast_exp(acc[0]), e1 = fast_exp(acc[1]);
            float e2 = fast_exp(acc[2]), e3 = fast_exp(acc[3]);
            rs0 += e0 + e1; rs1 += e2 + e3;
            __nv_bfloat162 h0 = __floats2bfloat162_rn(e0, e1);
            __nv_bfloat162 h1 = __floats2bfloat162_rn(e2, e3);
            sP[(wbase + g    )*68 + f*4 + q] = *(uint32_t*)&h0;
            sP[(wbase + g + 8)*68 + f*4 + q] = *(uint32_t*)&h1;
        }
        __syncthreads();
        // coalesced copy-out to g_P[b][i][j]
        for (int f = tid; f < 8192; f += 256) {
            int r = f >> 6, c = f & 63;
            ((uint32_t*)(g_P + (size_t)(b*NN + ibase + r)*NN + jb))[c] = sP[r*68 + c];
        }
    }

    // reduce rowsums over the 4 lanes of each quad
    rs0 += __shfl_xor_sync(0xffffffffu, rs0, 1);
    rs0 += __shfl_xor_sync(0xffffffffu, rs0, 2);
    rs1 += __shfl_xor_sync(0xffffffffu, rs1, 1);
    rs1 += __shfl_xor_sync(0xffffffffu, rs1, 2);
    if (q == 0) {
        g_rsum[(b*4 + quart)*NN + ibase + wbase + g]     = rs0;
        g_rsum[(b*4 + quart)*NN + ibase + wbase + g + 8] = rs1;
    }
}

// ---------------------------------------------------------------------------
// PV kernel: D[128i,128m] = sum_j P[i,j] V[m,j]; normalize + residual.
// grid (32 i-tiles, 4 m-tiles, BB), 256 threads (8 warps x 16 i-rows)
// ---------------------------------------------------------------------------
#define PV_A0 0
#define PV_A1 16384
#define PV_B0 32768
#define PV_B1 49152
#define PV_SINV (128*132*4)                 // 67584 (sO occupies [0,67584))
#define PV_SMEM (PV_SINV + 512)

__global__ __launch_bounds__(256, 2) void rsa_pv_kernel(
    const float* __restrict__ x,
    const float* __restrict__ gamma,
    float* __restrict__ out)
{
    extern __shared__ char smem[];
    const uint32_t sb = smem_u32(smem);
    const int tid  = threadIdx.x;
    const int wid  = tid >> 5, lane = tid & 31;
    const int g    = lane >> 2, q = lane & 3;
    const int b    = blockIdx.z, ibase = blockIdx.x * 128, mbase = blockIdx.y * 128;
    const int wbase = wid * 16;

    const uint32_t smA[2] = { sb + PV_A0, sb + PV_A1 };
    const uint32_t smB[2] = { sb + PV_B0, sb + PV_B1 };

    auto load_chunk = [&](int c, int p) {
        const int jb = c * 64;
#pragma unroll
        for (int it = 0; it < 4; it++) {
            int f = it*256 + tid;
            int r = f >> 3, cc = f & 7;
            uint32_t off = swoff(r, cc);
            cpasync16(smA[p] + off, g_P + (size_t)(b*NN + ibase + r)*NN + jb + cc*8);
            cpasync16(smB[p] + off, g_V + (size_t)(b*MM + mbase + r)*NN + jb + cc*8);
        }
        asm volatile("cp.async.commit_group;" ::: "memory");
    };

    float acc[16][4];
#pragma unroll
    for (int f = 0; f < 16; f++)
        acc[f][0] = acc[f][1] = acc[f][2] = acc[f][3] = 0.f;

    load_chunk(0, 0);

    const int sg = lane >> 3, rr = lane & 7;
    const int arow = wbase + ((sg & 1) << 3) + rr;
    const int brow = lane & 7, bco = lane >> 3;

    for (int c = 0; c < 64; c++) {
        const int p = c & 1;
        if (c + 1 < 64) {
            load_chunk(c + 1, p ^ 1);
            asm volatile("cp.async.wait_group 1;" ::: "memory");
        } else {
            asm volatile("cp.async.wait_group 0;" ::: "memory");
        }
        __syncthreads();

        uint32_t afr[4][4];
#pragma unroll
        for (int ks = 0; ks < 4; ks++)
            ldm_x4(afr[ks], smA[p] + swoff(arow, 2*ks + (sg >> 1)));
#pragma unroll
        for (int f = 0; f < 16; f++) {
            uint32_t bfr[8];
            ldm_x4(bfr,     smB[p] + swoff(f*8 + brow, 0 + bco));
            ldm_x4(bfr + 4, smB[p] + swoff(f*8 + brow, 4 + bco));
            mma_bf16(acc[f], afr[0], bfr);
            mma_bf16(acc[f], afr[1], bfr + 2);
            mma_bf16(acc[f], afr[2], bfr + 4);
            mma_bf16(acc[f], afr[3], bfr + 6);
        }
        __syncthreads();   // all warps done reading buffer p before it reloads
    }

    // epilogue: rowsum inverses + stage D into smem (reuses A/B buffers)
    float* sO   = (float*)smem;                 // [128 m][132]
    float* sInv = (float*)(smem + PV_SINV);     // [128]
    if (tid < 128) {
        int i = ibase + tid;
        float rs = g_rsum[(b*4 + 0)*NN + i] + g_rsum[(b*4 + 1)*NN + i]
                 + g_rsum[(b*4 + 2)*NN + i] + g_rsum[(b*4 + 3)*NN + i];
        sInv[tid] = 1.0f / rs;
    }
#pragma unroll
    for (int f = 0; f < 16; f++) {
        int m0 = f*8 + q*2;
        sO[(m0    )*132 + wbase + g]     = acc[f][0];
        sO[(m0 + 1)*132 + wbase + g]     = acc[f][1];
        sO[(m0    )*132 + wbase + g + 8] = acc[f][2];
        sO[(m0 + 1)*132 + wbase + g + 8] = acc[f][3];
    }
    __syncthreads();

    const float gm = gamma[0];
    for (int idx = tid; idx < 128*128; idx += 256) {
        int m = idx >> 7, i = idx & 127;
        size_t gi = (size_t)(b*MM + mbase + m)*NN + ibase + i;
        out[gi] = gm * x[gi] + sO[m*132 + i] * sInv[i];
    }
}

// ---------------------------------------------------------------------------
extern "C" void kernel_launch(void* const* d_in, const int* in_sizes, int n_in,
                              void* d_out, int out_size)
{
    const float* x     = (const float*)d_in[0];
    const float* Wk    = (const float*)d_in[1];
    const float* bk    = (const float*)d_in[2];
    const float* Wq    = (const float*)d_in[3];
    const float* bq    = (const float*)d_in[4];
    const float* Wv    = (const float*)d_in[5];
    const float* bv    = (const float*)d_in[6];
    const float* gamma = (const float*)d_in[7];
    float* out = (float*)d_out;

    cudaFuncSetAttribute(rsa_qk_kernel,
                         cudaFuncAttributeMaxDynamicSharedMemorySize, QK_SMEM);
    cudaFuncSetAttribute(rsa_pv_kernel,
                         cudaFuncAttributeMaxDynamicSharedMemorySize, PV_SMEM);

    rsa_proj_kernel<<<BB*DD*16, 256>>>(x, Wk, bk, Wq, bq, Wv, bv);

    dim3 gqk(32, 4, BB);
    rsa_qk_kernel<<<gqk, 256, QK_SMEM>>>();

    dim3 gpv(32, 4, BB);
    rsa_pv_kernel<<<gpv, 256, PV_SMEM>>>(x, gamma, out);
}